// round 5
// baseline (speedup 1.0000x reference)
#include <cuda_runtime.h>
#include <cuda_bf16.h>
#include <cstdint>

// LayerHypercube: out[b, f*1024+o] = sum_j x[b, o^(1<<j)] * w[f,j,o] + bias[f,o] + x[b,o]
// B=2048, F=16, O=IN=1024, BITS=10. fm[f,j,o] == o^(1<<j) (computed, not loaded).
//
// Block owns a 64-wide o-tile. x[o^2^j] for o in tile only touches 5 64-float
// chunks of the row: tile, tile^64, tile^128, tile^256, tile^512. Stage ONLY
// those (1.25KB/row, not 4KB). All math in packed f32x2 (Blackwell FFMA2).

#define BATCH   2048
#define INSZ    1024
#define OUTSZ   1024
#define NFM     16
#define NBITS   10

#define THREADS 128
#define OG      16
#define OTILE   64
#define ROWS    32              // 16 pairs per block
#define PAIRS   (ROWS / 2)
#define OBLOCKS (OUTSZ / OTILE) // 16
#define BBLOCKS (BATCH / ROWS)  // 64
#define NBUF    3

// smem geometry (bytes): buffer = 2 rows x 5 chunks x 16 float4 = 2560B
#define CHUNK_B   256
#define ROW_B     (5 * CHUNK_B)     // 1280
#define BUF_B     (2 * ROW_B)       // 2560

typedef unsigned long long ull;

__device__ __forceinline__ void cp16(uint32_t dst_smem, const void* src_gmem) {
    asm volatile("cp.async.cg.shared.global [%0], [%1], 16;\n"
                 :: "r"(dst_smem), "l"(src_gmem));
}
__device__ __forceinline__ void cp_commit() { asm volatile("cp.async.commit_group;\n"); }
__device__ __forceinline__ void cp_wait1()  { asm volatile("cp.async.wait_group 1;\n"); }

__device__ __forceinline__ void fma2(ull& d, ull a, ull b) {
    asm("fma.rn.f32x2 %0, %1, %2, %0;" : "+l"(d) : "l"(a), "l"(b));
}
__device__ __forceinline__ ull add2(ull a, ull b) {
    ull d; asm("add.rn.f32x2 %0, %1, %2;" : "=l"(d) : "l"(a), "l"(b)); return d;
}
__device__ __forceinline__ ull swap32(ull s) {   // (lo,hi) -> (hi,lo)
    ull d;
    asm("{ .reg .b32 a, b; mov.b64 {a, b}, %1; mov.b64 %0, {b, a}; }"
        : "=l"(d) : "l"(s));
    return d;
}
__device__ __forceinline__ void stcs2(void* p, ull lo, ull hi) {
    asm volatile("st.global.cs.v2.b64 [%0], {%1, %2};" :: "l"(p), "l"(lo), "l"(hi));
}

__global__ __launch_bounds__(THREADS, 4)
void hypercube_kernel(const float* __restrict__ x,
                      const float* __restrict__ w,
                      const float* __restrict__ bias,
                      float* __restrict__ out)
{
    __shared__ float4 sbuf[NBUF * 2 * 5 * 16];   // 7680 B

    const int tid   = threadIdx.x;
    const int og    = tid & (OG - 1);
    const int fp    = tid >> 4;
    const int obase = blockIdx.x * OTILE + og * 4;
    const int row0  = blockIdx.y * ROWS;
    const int B0    = blockIdx.x * OTILE;        // tile base (floats)

    // ---- weights & bias -> registers as f32x2 pairs (80 + 8 regs) ----
    ull w0l[NBITS], w0h[NBITS], w1l[NBITS], w1h[NBITS];
#pragma unroll
    for (int j = 0; j < NBITS; j++) {
        ulonglong2 t0 = *reinterpret_cast<const ulonglong2*>(
            w + ((fp * NBITS + j) * OUTSZ + obase));
        ulonglong2 t1 = *reinterpret_cast<const ulonglong2*>(
            w + (((fp + 8) * NBITS + j) * OUTSZ + obase));
        w0l[j] = t0.x; w0h[j] = t0.y;
        w1l[j] = t1.x; w1h[j] = t1.y;
    }
    ulonglong2 bb0 = *reinterpret_cast<const ulonglong2*>(bias + fp * OUTSZ + obase);
    ulonglong2 bb1 = *reinterpret_cast<const ulonglong2*>(bias + (fp + 8) * OUTSZ + obase);

    // ---- cp.async unit assignment: 160 16B units per pair (2 rows x 5 chunks x 16) ----
    // unit u: r = u<80?0:1, t = u-80r, c = t>>4, i = t&15
    // thread tid takes unit tid; threads 0..31 also take unit 128+tid.
    const int cb[5] = { B0, B0 ^ 64, B0 ^ 128, B0 ^ 256, B0 ^ 512 };  // float offsets in row

    int r1 = (tid < 80) ? 0 : 1;
    int t1 = tid - 80 * r1;
    int c1 = t1 >> 4, i1 = t1 & 15;
    const int srcOff1 = r1 * 4096 + cb[c1] * 4 + i1 * 16;     // bytes rel. pair base in x
    const int dstOff1 = r1 * ROW_B + c1 * CHUNK_B + i1 * 16;  // bytes rel. buffer base

    int c2 = 3 + (tid >> 4);          // valid for tid<32: tid<16 -> c=3, else c=4
    int i2 = tid & 15;
    const int srcOff2 = 4096 + cb[c2 & 7] * 4 + i2 * 16;      // r=1
    const int dstOff2 = ROW_B + (c2 & 7) * CHUNK_B + i2 * 16;

    const uint32_t sbase = (uint32_t)__cvta_generic_to_shared(sbuf);
    const char*    xpb   = reinterpret_cast<const char*>(x + (size_t)row0 * INSZ);

    auto issue_pair = [&](int bufIdx, int pair) {
        const char* base = xpb + (size_t)pair * 8192;
        uint32_t db = sbase + bufIdx * BUF_B;
        cp16(db + dstOff1, base + srcOff1);
        if (tid < 32) cp16(db + dstOff2, base + srcOff2);
    };

    issue_pair(0, 0); cp_commit();
    issue_pair(1, 1); cp_commit();

    float* op = out + (size_t)row0 * (NFM * OUTSZ) + fp * OUTSZ + obase;

    const int o1 = og ^ 1, o2 = og ^ 2, o4 = og ^ 4, o8 = og ^ 8;

    int cur = 0;
    for (int s = 0; s < PAIRS; s++) {
        cp_wait1();
        __syncthreads();

        int nxt = cur + 2; if (nxt >= NBUF) nxt -= NBUF;
        if (s + 2 < PAIRS) issue_pair(nxt, s + 2);
        cp_commit();

        const float4* rbA = sbuf + cur * (BUF_B / 16);        // row A chunks
        const float4* rbB = rbA + (ROW_B / 16);               // row B chunks

        // own values
        const ulonglong2 P = *reinterpret_cast<const ulonglong2*>(&rbA[og]);
        const ulonglong2 Q = *reinterpret_cast<const ulonglong2*>(&rbB[og]);
        const ull pswl = swap32(P.x), pswh = swap32(P.y);
        const ull qswl = swap32(Q.x), qswh = swap32(Q.y);

        // acc = bias + tiled x
        ull a0l = add2(bb0.x, P.x), a0h = add2(bb0.y, P.y);
        ull a1l = add2(bb1.x, P.x), a1h = add2(bb1.y, P.y);
        ull c0l = add2(bb0.x, Q.x), c0h = add2(bb0.y, Q.y);
        ull c1l = add2(bb1.x, Q.x), c1h = add2(bb1.y, Q.y);

        // j=0: x[o^1] -> per-pair swap
        fma2(a0l, w0l[0], pswl); fma2(a0h, w0h[0], pswh);
        fma2(a1l, w1l[0], pswl); fma2(a1h, w1h[0], pswh);
        fma2(c0l, w0l[0], qswl); fma2(c0h, w0h[0], qswh);
        fma2(c1l, w1l[0], qswl); fma2(c1h, w1h[0], qswh);

        // j=1: x[o^2] -> half reversal (free: operand order)
        fma2(a0l, w0l[1], P.y);  fma2(a0h, w0h[1], P.x);
        fma2(a1l, w1l[1], P.y);  fma2(a1h, w1h[1], P.x);
        fma2(c0l, w0l[1], Q.y);  fma2(c0h, w0h[1], Q.x);
        fma2(c1l, w1l[1], Q.y);  fma2(c1h, w1h[1], Q.x);

        // j=2..5: gathers within chunk 0 (og XOR 1,2,4,8)
#pragma unroll
        for (int j = 2; j < 6; j++) {
            const int gi = (j == 2) ? o1 : (j == 3) ? o2 : (j == 4) ? o4 : o8;
            const ulonglong2 U = *reinterpret_cast<const ulonglong2*>(&rbA[gi]);
            const ulonglong2 V = *reinterpret_cast<const ulonglong2*>(&rbB[gi]);
            fma2(a0l, w0l[j], U.x); fma2(a0h, w0h[j], U.y);
            fma2(a1l, w1l[j], U.x); fma2(a1h, w1h[j], U.y);
            fma2(c0l, w0l[j], V.x); fma2(c0h, w0h[j], V.y);
            fma2(c1l, w1l[j], V.x); fma2(c1h, w1h[j], V.y);
        }

        // j=6..9: gathers from chunks 1..4 at the SAME og
#pragma unroll
        for (int j = 6; j < NBITS; j++) {
            const int gi = (j - 5) * 16 + og;
            const ulonglong2 U = *reinterpret_cast<const ulonglong2*>(&rbA[gi]);
            const ulonglong2 V = *reinterpret_cast<const ulonglong2*>(&rbB[gi]);
            fma2(a0l, w0l[j], U.x); fma2(a0h, w0h[j], U.y);
            fma2(a1l, w1l[j], U.x); fma2(a1h, w1h[j], U.y);
            fma2(c0l, w0l[j], V.x); fma2(c0h, w0h[j], V.y);
            fma2(c1l, w1l[j], V.x); fma2(c1h, w1h[j], V.y);
        }

        stcs2(op,                          a0l, a0h);
        stcs2(op + 8 * OUTSZ,              a1l, a1h);
        stcs2(op + NFM * OUTSZ,            c0l, c0h);
        stcs2(op + NFM * OUTSZ + 8 * OUTSZ, c1l, c1h);

        op += 2 * NFM * OUTSZ;
        cur = cur + 1; if (cur >= NBUF) cur -= NBUF;
    }
}

extern "C" void kernel_launch(void* const* d_in, const int* in_sizes, int n_in,
                              void* d_out, int out_size)
{
    const float* x    = (const float*)d_in[0];
    const float* w    = (const float*)d_in[1];
    const float* bias = (const float*)d_in[2];
    // d_in[3] = fm (int32) — values are o^(1<<j), computed inline instead.
    float* out = (float*)d_out;

    dim3 grid(OBLOCKS, BBLOCKS);
    hypercube_kernel<<<grid, THREADS>>>(x, w, bias, out);
}

// round 6
// speedup vs baseline: 1.1109x; 1.1109x over previous
#include <cuda_runtime.h>
#include <cuda_bf16.h>
#include <cstdint>

// LayerHypercube: out[b, f*1024+o] = sum_j x[b, o^(1<<j)] * w[f,j,o] + bias[f,o] + x[b,o]
// B=2048, F=16, O=IN=1024, BITS=10. fm[f,j,o] == o^(1<<j) (computed, not loaded).
//
// j=0,1: in-register permutations. j=2..5: shfl.bfly (partner lane holds it).
// j=6..9: LDS from the 4 remote 64-float chunks (tile^64,^128,^256,^512).
// Math in packed f32x2 (Blackwell FFMA2).

#define BATCH   2048
#define INSZ    1024
#define OUTSZ   1024
#define NFM     16
#define NBITS   10

#define THREADS 128
#define OG      16
#define OTILE   64
#define ROWS    32              // 16 pairs per block
#define PAIRS   (ROWS / 2)
#define OBLOCKS (OUTSZ / OTILE) // 16
#define BBLOCKS (BATCH / ROWS)  // 64
#define NBUF    3

#define CHUNK_B   256
#define ROW_B     (5 * CHUNK_B)     // 1280
#define BUF_B     (2 * ROW_B)       // 2560

typedef unsigned long long ull;

__device__ __forceinline__ void cp16(uint32_t dst_smem, const void* src_gmem) {
    asm volatile("cp.async.cg.shared.global [%0], [%1], 16;\n"
                 :: "r"(dst_smem), "l"(src_gmem));
}
__device__ __forceinline__ void cp_commit() { asm volatile("cp.async.commit_group;\n"); }
__device__ __forceinline__ void cp_wait1()  { asm volatile("cp.async.wait_group 1;\n"); }

__device__ __forceinline__ void fma2(ull& d, ull a, ull b) {
    asm("fma.rn.f32x2 %0, %1, %2, %0;" : "+l"(d) : "l"(a), "l"(b));
}
__device__ __forceinline__ ull add2(ull a, ull b) {
    ull d; asm("add.rn.f32x2 %0, %1, %2;" : "=l"(d) : "l"(a), "l"(b)); return d;
}
__device__ __forceinline__ ull pk(float lo, float hi) {
    ull d; asm("mov.b64 %0, {%1, %2};" : "=l"(d) : "f"(lo), "f"(hi)); return d;
}
__device__ __forceinline__ void stcs2(void* p, ull lo, ull hi) {
    asm volatile("st.global.cs.v2.b64 [%0], {%1, %2};" :: "l"(p), "l"(lo), "l"(hi));
}

__global__ __launch_bounds__(THREADS, 4)
void hypercube_kernel(const float* __restrict__ x,
                      const float* __restrict__ w,
                      const float* __restrict__ bias,
                      float* __restrict__ out)
{
    __shared__ float4 sbuf[NBUF * 2 * 5 * 16];   // 7680 B

    const int tid   = threadIdx.x;
    const int og    = tid & (OG - 1);
    const int fp    = tid >> 4;
    const int obase = blockIdx.x * OTILE + og * 4;
    const int row0  = blockIdx.y * ROWS;
    const int B0    = blockIdx.x * OTILE;

    // ---- weights & bias -> registers as f32x2 pairs ----
    ull w0l[NBITS], w0h[NBITS], w1l[NBITS], w1h[NBITS];
#pragma unroll
    for (int j = 0; j < NBITS; j++) {
        ulonglong2 t0 = *reinterpret_cast<const ulonglong2*>(
            w + ((fp * NBITS + j) * OUTSZ + obase));
        ulonglong2 t1 = *reinterpret_cast<const ulonglong2*>(
            w + (((fp + 8) * NBITS + j) * OUTSZ + obase));
        w0l[j] = t0.x; w0h[j] = t0.y;
        w1l[j] = t1.x; w1h[j] = t1.y;
    }
    ulonglong2 bb0 = *reinterpret_cast<const ulonglong2*>(bias + fp * OUTSZ + obase);
    ulonglong2 bb1 = *reinterpret_cast<const ulonglong2*>(bias + (fp + 8) * OUTSZ + obase);

    // ---- cp.async staging: 160 16B units per pair (2 rows x 5 chunks x 16) ----
    const int cb[5] = { B0, B0 ^ 64, B0 ^ 128, B0 ^ 256, B0 ^ 512 };

    int r1 = (tid < 80) ? 0 : 1;
    int t1 = tid - 80 * r1;
    int c1 = t1 >> 4, i1 = t1 & 15;
    const int srcOff1 = r1 * 4096 + cb[c1] * 4 + i1 * 16;
    const int dstOff1 = r1 * ROW_B + c1 * CHUNK_B + i1 * 16;

    int c2 = 3 + (tid >> 4);          // valid for tid<32
    int i2 = tid & 15;
    const int srcOff2 = 4096 + cb[c2 & 7] * 4 + i2 * 16;
    const int dstOff2 = ROW_B + (c2 & 7) * CHUNK_B + i2 * 16;

    const uint32_t sbase = (uint32_t)__cvta_generic_to_shared(sbuf);
    const char*    xpb   = reinterpret_cast<const char*>(x + (size_t)row0 * INSZ);

    auto issue_pair = [&](int bufIdx, int pair) {
        const char* base = xpb + (size_t)pair * 8192;
        uint32_t db = sbase + bufIdx * BUF_B;
        cp16(db + dstOff1, base + srcOff1);
        if (tid < 32) cp16(db + dstOff2, base + srcOff2);
    };

    issue_pair(0, 0); cp_commit();
    issue_pair(1, 1); cp_commit();

    float* op = out + (size_t)row0 * (NFM * OUTSZ) + fp * OUTSZ + obase;

    int cur = 0;
    for (int s = 0; s < PAIRS; s++) {
        cp_wait1();
        __syncthreads();

        int nxt = cur + 2; if (nxt >= NBUF) nxt -= NBUF;
        if (s + 2 < PAIRS) issue_pair(nxt, s + 2);
        cp_commit();

        const float4* rbA = sbuf + cur * (BUF_B / 16);
        const float4* rbB = rbA + (ROW_B / 16);

        // own values as scalars (packs below are register aliasing, free)
        const float4 p = rbA[og];
        const float4 q = rbB[og];
        const ull Pl = pk(p.x, p.y), Ph = pk(p.z, p.w);
        const ull Ql = pk(q.x, q.y), Qh = pk(q.z, q.w);

        // acc = bias + tiled x
        ull a0l = add2(bb0.x, Pl), a0h = add2(bb0.y, Ph);
        ull a1l = add2(bb1.x, Pl), a1h = add2(bb1.y, Ph);
        ull c0l = add2(bb0.x, Ql), c0h = add2(bb0.y, Qh);
        ull c1l = add2(bb1.x, Ql), c1h = add2(bb1.y, Qh);

        // j=0: x[o^1] -> per-pair swap (free re-pack)
        {
            const ull Psl = pk(p.y, p.x), Psh = pk(p.w, p.z);
            const ull Qsl = pk(q.y, q.x), Qsh = pk(q.w, q.z);
            fma2(a0l, w0l[0], Psl); fma2(a0h, w0h[0], Psh);
            fma2(a1l, w1l[0], Psl); fma2(a1h, w1h[0], Psh);
            fma2(c0l, w0l[0], Qsl); fma2(c0h, w0h[0], Qsh);
            fma2(c1l, w1l[0], Qsl); fma2(c1h, w1h[0], Qsh);
        }

        // j=1: x[o^2] -> half reversal (operand order, free)
        fma2(a0l, w0l[1], Ph);  fma2(a0h, w0h[1], Pl);
        fma2(a1l, w1l[1], Ph);  fma2(a1h, w1h[1], Pl);
        fma2(c0l, w0l[1], Qh);  fma2(c0h, w0h[1], Ql);
        fma2(c1l, w1l[1], Qh);  fma2(c1h, w1h[1], Ql);

        // j=2..5: partner lane (lane^m) holds x[o^(4<<k)] -> shfl.bfly, no LDS
#pragma unroll
        for (int k = 0; k < 4; k++) {
            const int m = 1 << k;      // lane xor = og xor
            const int j = k + 2;
            const float ux = __shfl_xor_sync(0xffffffffu, p.x, m);
            const float uy = __shfl_xor_sync(0xffffffffu, p.y, m);
            const float uz = __shfl_xor_sync(0xffffffffu, p.z, m);
            const float uw = __shfl_xor_sync(0xffffffffu, p.w, m);
            const float vx = __shfl_xor_sync(0xffffffffu, q.x, m);
            const float vy = __shfl_xor_sync(0xffffffffu, q.y, m);
            const float vz = __shfl_xor_sync(0xffffffffu, q.z, m);
            const float vw = __shfl_xor_sync(0xffffffffu, q.w, m);
            const ull Ulo = pk(ux, uy), Uhi = pk(uz, uw);
            const ull Vlo = pk(vx, vy), Vhi = pk(vz, vw);
            fma2(a0l, w0l[j], Ulo); fma2(a0h, w0h[j], Uhi);
            fma2(a1l, w1l[j], Ulo); fma2(a1h, w1h[j], Uhi);
            fma2(c0l, w0l[j], Vlo); fma2(c0h, w0h[j], Vhi);
            fma2(c1l, w1l[j], Vlo); fma2(c1h, w1h[j], Vhi);
        }

        // j=6..9: LDS gathers from chunks 1..4 at the SAME og
#pragma unroll
        for (int j = 6; j < NBITS; j++) {
            const int gi = (j - 5) * 16 + og;
            const ulonglong2 U = *reinterpret_cast<const ulonglong2*>(&rbA[gi]);
            const ulonglong2 V = *reinterpret_cast<const ulonglong2*>(&rbB[gi]);
            fma2(a0l, w0l[j], U.x); fma2(a0h, w0h[j], U.y);
            fma2(a1l, w1l[j], U.x); fma2(a1h, w1h[j], U.y);
            fma2(c0l, w0l[j], V.x); fma2(c0h, w0h[j], V.y);
            fma2(c1l, w1l[j], V.x); fma2(c1h, w1h[j], V.y);
        }

        stcs2(op,                           a0l, a0h);
        stcs2(op + 8 * OUTSZ,               a1l, a1h);
        stcs2(op + NFM * OUTSZ,             c0l, c0h);
        stcs2(op + NFM * OUTSZ + 8 * OUTSZ, c1l, c1h);

        op += 2 * NFM * OUTSZ;
        cur = cur + 1; if (cur >= NBUF) cur -= NBUF;
    }
}

extern "C" void kernel_launch(void* const* d_in, const int* in_sizes, int n_in,
                              void* d_out, int out_size)
{
    const float* x    = (const float*)d_in[0];
    const float* w    = (const float*)d_in[1];
    const float* bias = (const float*)d_in[2];
    // d_in[3] = fm (int32) — values are o^(1<<j), computed inline instead.
    float* out = (float*)d_out;

    dim3 grid(OBLOCKS, BBLOCKS);
    hypercube_kernel<<<grid, THREADS>>>(x, w, bias, out);
}